// round 17
// baseline (speedup 1.0000x reference)
#include <cuda_runtime.h>
#include <cuda.h>
#include <cuda_bf16.h>
#include <cuda_fp16.h>
#include <math.h>
#include <stdint.h>

#define D_DIM 256
#define O_DIM 32
#define NMAX 50000
#define EMAX 800000

// ---------------- scratch (static device globals; no runtime allocation) ---
__device__ __align__(1024) __half g_Bh[(size_t)NMAX * D_DIM]; // h1 fp16
__device__ __align__(1024) __half g_Ch[(size_t)NMAX * D_DIM]; // nb fp16
__device__ __align__(1024) __half g_Yh[(size_t)NMAX * D_DIM]; // dinv*nb fp16
__device__ __align__(1024) __nv_bfloat16 g_Ah[(size_t)NMAX * D_DIM]; // input hi
__device__ __align__(1024) __nv_bfloat16 g_Al[(size_t)NMAX * D_DIM]; // input lo
__device__ __align__(1024) __nv_bfloat16 g_Wh[2][512 * 256];  // weights [n][k] hi
__device__ __align__(1024) __nv_bfloat16 g_Wl[2][512 * 256];  // weights [n][k] lo
__device__ float g_biasC[2][512];
__device__ float g_WfP[2][4][256 * 256];      // partial W@Wn (layer, k-quarter)
__device__ float g_bf[2][256];                // b @ Wn + bn per layer
__device__ float g_dinv[NMAX];
__device__ int   g_cnt[NMAX];
__device__ int   g_rowstart[NMAX];
__device__ int   g_cursor[NMAX];
__device__ int   g_colidx[EMAX];
__device__ int   g_base;                      // global slot cursor

// ================= helpers =================================================
__device__ __forceinline__ uint32_t smem_u32(const void* p) {
    uint32_t a;
    asm("{ .reg .u64 t; cvta.to.shared.u64 t, %1; cvt.u32.u64 %0, t; }"
        : "=r"(a) : "l"(p));
    return a;
}
__device__ __forceinline__ void ldsm_x4(uint32_t* r, uint32_t addr) {
    asm volatile("ldmatrix.sync.aligned.m8n8.x4.shared.b16 {%0,%1,%2,%3}, [%4];"
                 : "=r"(r[0]), "=r"(r[1]), "=r"(r[2]), "=r"(r[3]) : "r"(addr));
}
__device__ __forceinline__ void mma_bf16(float* c, const uint32_t* a,
                                         uint32_t b0, uint32_t b1) {
    asm volatile(
        "mma.sync.aligned.m16n8k16.row.col.f32.bf16.bf16.f32 "
        "{%0,%1,%2,%3}, {%4,%5,%6,%7}, {%8,%9}, {%0,%1,%2,%3};"
        : "+f"(c[0]), "+f"(c[1]), "+f"(c[2]), "+f"(c[3])
        : "r"(a[0]), "r"(a[1]), "r"(a[2]), "r"(a[3]), "r"(b0), "r"(b1));
}
__device__ __forceinline__ void tma2d(uint32_t smem, const CUtensorMap* map,
                                      int x, int y, uint32_t mbar) {
    asm volatile(
        "cp.async.bulk.tensor.2d.shared::cta.global.tile.mbarrier::complete_tx::bytes "
        "[%0], [%1, {%2, %3}], [%4];"
        :: "r"(smem), "l"(map), "r"(x), "r"(y), "r"(mbar) : "memory");
}
#define MBAR_INIT(mb, c)  asm volatile("mbarrier.init.shared.b64 [%0], %1;" :: "r"(mb), "r"(c) : "memory")
#define MBAR_EXPECT_TX(mb, tx) asm volatile("mbarrier.arrive.expect_tx.shared.b64 _, [%0], %1;" :: "r"(mb), "r"(tx) : "memory")
#define MBAR_WAIT(mb, par) do {                                              \
    uint32_t _mb = (mb), _p = (par), _done;                                  \
    asm volatile("{\n\t.reg .pred p;\n\t"                                    \
        "mbarrier.try_wait.parity.acquire.cta.shared::cta.b64 p, [%1], %2;\n\t" \
        "selp.b32 %0, 1, 0, p;\n\t}" : "=r"(_done) : "r"(_mb), "r"(_p) : "memory"); \
    if (!_done) {                                                            \
        asm volatile("{\n\t.reg .pred P1;\n\t"                               \
            "WL_%=:\n\t"                                                     \
            "mbarrier.try_wait.parity.acquire.cta.shared::cta.b64 P1, [%0], %1, 0x989680;\n\t" \
            "@P1 bra.uni WD_%=;\n\tbra.uni WL_%=;\n\tWD_%=:\n\t}"            \
            :: "r"(_mb), "r"(_p) : "memory");                                \
    }                                                                        \
} while (0)
#define SW128(off) ((off) ^ (((off) >> 3) & 0x70))

// ---------------- CSR build (scan-free) ------------------------------------
__global__ void count_edges_kernel(const int* __restrict__ row, int e) {
    int i = blockIdx.x * blockDim.x + threadIdx.x;
    if (i < e) atomicAdd(&g_cnt[row[i]], 1);
}
__global__ void offsets_kernel(int n) {
    int i = blockIdx.x * blockDim.x + threadIdx.x;
    int lane = threadIdx.x & 31;
    int c = (i < n) ? g_cnt[i] : 0;
    int incl = c;
    #pragma unroll
    for (int o = 1; o < 32; o <<= 1) {
        int v = __shfl_up_sync(0xffffffffu, incl, o);
        if (lane >= o) incl += v;
    }
    int total = __shfl_sync(0xffffffffu, incl, 31);
    int base = 0;
    if (lane == 31 && total > 0) base = atomicAdd(&g_base, total);
    base = __shfl_sync(0xffffffffu, base, 31);
    if (i < n) {
        int start = base + incl - c;
        g_rowstart[i] = start;
        g_cursor[i]   = start;
        g_dinv[i]     = rsqrtf((float)(c + 1));
    }
}
__global__ void fill_csr_kernel(const int* __restrict__ row,
                                const int* __restrict__ col, int e) {
    int i = blockIdx.x * blockDim.x + threadIdx.x;
    if (i < e) {
        int p = atomicAdd(&g_cursor[row[i]], 1);
        g_colidx[p] = col[i];
    }
}

// ---------------- weight prep ---------------------------------------------
// smem-tiled partial Wf = W @ Wn, k-split x4: grid (8,8,8) z=layer*4+part
__global__ void fuse_wf_kernel(const float* __restrict__ W0,
                               const float* __restrict__ Wn0,
                               const float* __restrict__ W1,
                               const float* __restrict__ Wn1) {
    __shared__ float sW[32][33], sWn[32][33];
    int layer = blockIdx.z >> 2, part = blockIdx.z & 3;
    const float* W  = layer ? W1  : W0;
    const float* Wn = layer ? Wn1 : Wn0;
    int k0 = blockIdx.x * 32, n0 = blockIdx.y * 32;
    int tx = threadIdx.x, ty = threadIdx.y;
    float acc[4] = {0.f, 0.f, 0.f, 0.f};
    int jbeg = part * 64, jend = jbeg + 64;
    for (int j0 = jbeg; j0 < jend; j0 += 32) {
        #pragma unroll
        for (int i = 0; i < 4; i++) {
            sW[ty + 8 * i][tx]  = W[(k0 + ty + 8 * i) * 256 + j0 + tx];
            sWn[ty + 8 * i][tx] = Wn[(j0 + ty + 8 * i) * 256 + n0 + tx];
        }
        __syncthreads();
        #pragma unroll
        for (int j = 0; j < 32; j++) {
            float wn = sWn[j][tx];
            #pragma unroll
            for (int i = 0; i < 4; i++)
                acc[i] = fmaf(sW[ty + 8 * i][j], wn, acc[i]);
        }
        __syncthreads();
    }
    #pragma unroll
    for (int i = 0; i < 4; i++)
        g_WfP[layer][part][(k0 + ty + 8 * i) * 256 + n0 + tx] = acc[i];
}
// bf = b @ Wn + bn (both layers)
__global__ void fuse_b_kernel(const float* __restrict__ b0,
                              const float* __restrict__ Wn0,
                              const float* __restrict__ bn0,
                              const float* __restrict__ b1,
                              const float* __restrict__ Wn1,
                              const float* __restrict__ bn1) {
    int layer = blockIdx.x;
    const float* b  = layer ? b1  : b0;
    const float* Wn = layer ? Wn1 : Wn0;
    const float* bn = layer ? bn1 : bn0;
    int n = threadIdx.x;
    float acc = bn[n];
    #pragma unroll 8
    for (int j = 0; j < 256; j++)
        acc = fmaf(__ldg(b + j), Wn[(size_t)j * 256 + n], acc);
    g_bf[layer][n] = acc;
}
__global__ void pack_w_kernel(const float* __restrict__ W0,
                              const float* __restrict__ b0,
                              const float* __restrict__ W1,
                              const float* __restrict__ b1) {
    __shared__ float s[32][33];
    int layer = blockIdx.z;
    const float* W = layer ? W1 : W0;
    const float* b = layer ? b1 : b0;
    int k0 = blockIdx.x * 32, n0 = blockIdx.y * 32;
    int tx = threadIdx.x, ty = threadIdx.y;
    #pragma unroll
    for (int i = 0; i < 4; i++) {
        int k = k0 + ty + i * 8;
        float v;
        if (n0 < 256) v = W[k * 256 + n0 + tx];
        else {
            int idx = k * 256 + (n0 - 256) + tx;
            v = (g_WfP[layer][0][idx] + g_WfP[layer][1][idx])
              + (g_WfP[layer][2][idx] + g_WfP[layer][3][idx]);
        }
        s[ty + i * 8][tx] = v;
    }
    __syncthreads();
    #pragma unroll
    for (int i = 0; i < 4; i++) {
        int n = n0 + ty + i * 8;
        float w = s[tx][ty + i * 8];
        __nv_bfloat16 hi = __float2bfloat16(w);
        g_Wh[layer][n * 256 + k0 + tx] = hi;
        g_Wl[layer][n * 256 + k0 + tx] = __float2bfloat16(w - __bfloat162float(hi));
    }
    if (blockIdx.x == 0 && tx == 0) {
        #pragma unroll
        for (int i = 0; i < 4; i++) {
            int n = n0 + ty + i * 8;
            g_biasC[layer][n] = (n < 256) ? b[n] : g_bf[layer][n - 256];
        }
    }
}
__global__ void split_kernel(const float* __restrict__ x, int total4) {
    int i = blockIdx.x * blockDim.x + threadIdx.x;
    if (i < total4) {
        float4 v = reinterpret_cast<const float4*>(x)[i];
        __nv_bfloat16 h0 = __float2bfloat16(v.x), h1 = __float2bfloat16(v.y);
        __nv_bfloat16 h2 = __float2bfloat16(v.z), h3 = __float2bfloat16(v.w);
        __nv_bfloat162 hA, hB, lA, lB;
        hA.x = h0; hA.y = h1; hB.x = h2; hB.y = h3;
        lA.x = __float2bfloat16(v.x - __bfloat162float(h0));
        lA.y = __float2bfloat16(v.y - __bfloat162float(h1));
        lB.x = __float2bfloat16(v.z - __bfloat162float(h2));
        lB.y = __float2bfloat16(v.w - __bfloat162float(h3));
        reinterpret_cast<__nv_bfloat162*>(g_Ah)[i * 2]     = hA;
        reinterpret_cast<__nv_bfloat162*>(g_Ah)[i * 2 + 1] = hB;
        reinterpret_cast<__nv_bfloat162*>(g_Al)[i * 2]     = lA;
        reinterpret_cast<__nv_bfloat162*>(g_Al)[i * 2 + 1] = lB;
    }
}

// ---------------- HMMA GEMM: [B|C] = A @ Wcomb, split-bf16 x3, TMA loads ---
// 512 threads, 16 warps in 4x4 grid, warp tile 32x32.
// Epilogue: B half -> fp16 Bh; C half -> fp16 Ch + fp16 Yh=dinv*C.
#define STAGE_BYTES 65536
__global__ __launch_bounds__(512)
void hmma_gemm_kernel(const __grid_constant__ CUtensorMap tmAh,
                      const __grid_constant__ CUtensorMap tmAl,
                      const __grid_constant__ CUtensorMap tmWh,
                      const __grid_constant__ CUtensorMap tmWl,
                      int wyoff,
                      const float* __restrict__ bias,
                      __half* __restrict__ Bh, __half* __restrict__ Ch,
                      __half* __restrict__ Yh, const float* __restrict__ dinv,
                      int M)
{
    extern __shared__ char dsm_raw[];
    __shared__ __align__(8) unsigned long long s_mbar[2];
    uint32_t dynu = smem_u32(dsm_raw);
    uint32_t pad = ((dynu + 1023) & ~1023u) - dynu;
    uint32_t sb = dynu + pad;
    const uint32_t OFF_AH = 0, OFF_AL = 16384, OFF_BH = 32768, OFF_BL = 49152;

    int tid  = threadIdx.x;
    int warp = tid >> 5, lane = tid & 31;
    int brow = blockIdx.x * 128;
    int ncb  = blockIdx.y * 128;
    int wm   = (warp >> 2) * 32;
    int wn   = (warp & 3) * 32;

    uint32_t mb0 = smem_u32(&s_mbar[0]);
    uint32_t mb1 = smem_u32(&s_mbar[1]);
    if (tid == 0) { MBAR_INIT(mb0, 1); MBAR_INIT(mb1, 1); }
    __syncthreads();

    float acc[2][4][4];
    #pragma unroll
    for (int mi = 0; mi < 2; mi++)
        #pragma unroll
        for (int ni = 0; ni < 4; ni++)
            #pragma unroll
            for (int q = 0; q < 4; q++) acc[mi][ni][q] = 0.0f;

    auto load_chunk = [&](int chunk, int stage) {
        int k0 = chunk * 64;
        uint32_t sbase = sb + stage * STAGE_BYTES;
        uint32_t mb = stage ? mb1 : mb0;
        MBAR_EXPECT_TX(mb, (uint32_t)STAGE_BYTES);
        tma2d(sbase + OFF_AH, &tmAh, k0, brow, mb);
        tma2d(sbase + OFF_AL, &tmAl, k0, brow, mb);
        tma2d(sbase + OFF_BH, &tmWh, k0, wyoff + ncb, mb);
        tma2d(sbase + OFF_BL, &tmWl, k0, wyoff + ncb, mb);
    };

    if (tid == 0) load_chunk(0, 0);

    for (int chunk = 0; chunk < 4; chunk++) {
        int stage = chunk & 1;
        if (chunk < 3 && tid == 0) load_chunk(chunk + 1, stage ^ 1);
        MBAR_WAIT(stage ? mb1 : mb0, (chunk >> 1) & 1);

        uint32_t sbase = sb + stage * STAGE_BYTES;
        #pragma unroll
        for (int ks = 0; ks < 4; ks++) {
            uint32_t kb   = (uint32_t)(ks * 32 + ((lane >> 4) & 1) * 16);
            uint32_t kswz = kb ^ ((uint32_t)(lane & 7) << 4);
            uint32_t rsub = (uint32_t)((lane & 7) + ((lane >> 3) & 1) * 8);

            uint32_t adA = sbase + (wm + rsub) * 128 + kswz;
            uint32_t adB = sbase + (wn + rsub) * 128 + kswz;

            uint32_t a[2][4];                    // reused: hi then lo
            uint32_t bh[2][4], bl[2][4];
            #pragma unroll
            for (int mi = 0; mi < 2; mi++)
                ldsm_x4(a[mi], adA + OFF_AH + mi * 2048);
            #pragma unroll
            for (int nj = 0; nj < 2; nj++) {
                ldsm_x4(bh[nj], adB + OFF_BH + nj * 2048);
                ldsm_x4(bl[nj], adB + OFF_BL + nj * 2048);
            }
            #pragma unroll
            for (int mi = 0; mi < 2; mi++)
                #pragma unroll
                for (int ni = 0; ni < 4; ni++) {
                    int nj = ni >> 1, sel = ni & 1;
                    mma_bf16(acc[mi][ni], a[mi], bh[nj][sel], bh[nj][sel + 2]);
                    mma_bf16(acc[mi][ni], a[mi], bl[nj][sel], bl[nj][sel + 2]);
                }
            #pragma unroll
            for (int mi = 0; mi < 2; mi++)
                ldsm_x4(a[mi], adA + OFF_AL + mi * 2048);
            #pragma unroll
            for (int mi = 0; mi < 2; mi++)
                #pragma unroll
                for (int ni = 0; ni < 4; ni++) {
                    int nj = ni >> 1, sel = ni & 1;
                    mma_bf16(acc[mi][ni], a[mi], bh[nj][sel], bh[nj][sel + 2]);
                }
        }
        __syncthreads();
    }

    bool chalf = (ncb >= 256);
    int  cbase = chalf ? (ncb - 256) : ncb;
    #pragma unroll
    for (int mi = 0; mi < 2; mi++) {
        int row0 = brow + wm + mi * 16 + (lane >> 2);
        int row1 = row0 + 8;
        #pragma unroll
        for (int ni = 0; ni < 4; ni++) {
            int gcol = cbase + wn + ni * 8 + (lane & 3) * 2;
            float2 bb = *(const float2*)(bias + (chalf ? 256 : 0) + gcol);
            float2 v0, v1;
            v0.x = acc[mi][ni][0] + bb.x; v0.y = acc[mi][ni][1] + bb.y;
            v1.x = acc[mi][ni][2] + bb.x; v1.y = acc[mi][ni][3] + bb.y;
            if (!chalf) {
                if (row0 < M)
                    *(__half2*)(Bh + (size_t)row0 * 256 + gcol) =
                        __floats2half2_rn(v0.x, v0.y);
                if (row1 < M)
                    *(__half2*)(Bh + (size_t)row1 * 256 + gcol) =
                        __floats2half2_rn(v1.x, v1.y);
            } else {
                if (row0 < M) {
                    float di = dinv[row0];
                    *(__half2*)(Ch + (size_t)row0 * 256 + gcol) =
                        __floats2half2_rn(v0.x, v0.y);
                    *(__half2*)(Yh + (size_t)row0 * 256 + gcol) =
                        __floats2half2_rn(di * v0.x, di * v0.y);
                }
                if (row1 < M) {
                    float di = dinv[row1];
                    *(__half2*)(Ch + (size_t)row1 * 256 + gcol) =
                        __floats2half2_rn(v1.x, v1.y);
                    *(__half2*)(Yh + (size_t)row1 * 256 + gcol) =
                        __floats2half2_rn(di * v1.x, di * v1.y);
                }
            }
        }
    }
}

// ---------------- fused aggregate + mix + l2norm + relu -> bf16 hi/lo ------
__global__ __launch_bounds__(256)
void agg_combine_kernel(const __half* __restrict__ Bm, const __half* __restrict__ Ch,
                        const __half* __restrict__ Yh, int M)
{
    int i = blockIdx.x;
    int t = threadIdx.x;
    if (i >= M) return;

    int g = t >> 5;          // warp 0..7 = neighbor group
    int sl = t & 31;         // lane = feature chunk (8 halves)

    __shared__ int cols[256];
    __shared__ float sacc[8][256];
    __shared__ float wsum[8];

    int s = g_rowstart[i];
    int e = s + g_cnt[i];

    float facc[8];
    #pragma unroll
    for (int q = 0; q < 8; q++) facc[q] = 0.0f;

    for (int base = s; base < e; base += 256) {
        int m = min(256, e - base);
        if (t < m) cols[t] = g_colidx[base + t];
        __syncthreads();
        for (int j = g; j < m; j += 8) {
            const __half* yrow = Yh + (size_t)cols[j] * D_DIM + sl * 8;
            uint4 v = *reinterpret_cast<const uint4*>(yrow);
            const __half2* hp = reinterpret_cast<const __half2*>(&v);
            #pragma unroll
            for (int q = 0; q < 4; q++) {
                float2 f = __half22float2(hp[q]);
                facc[q * 2]     += f.x;
                facc[q * 2 + 1] += f.y;
            }
        }
        __syncthreads();
    }
    #pragma unroll
    for (int q = 0; q < 8; q++) sacc[g][sl * 8 + q] = facc[q];
    __syncthreads();

    float acc = 0.0f;
    #pragma unroll
    for (int g2 = 0; g2 < 8; g2++) acc += sacc[g2][t];

    float di = g_dinv[i];
    float nb = __half2float(Ch[(size_t)i * D_DIM + t]);
    float prop = di * acc + di * di * nb;
    float h = __half2float(Bm[(size_t)i * D_DIM + t]) + 0.5f * prop + 0.5f * nb;

    float v = h * h;
    #pragma unroll
    for (int o = 16; o > 0; o >>= 1)
        v += __shfl_xor_sync(0xffffffffu, v, o);
    if ((t & 31) == 0) wsum[t >> 5] = v;
    __syncthreads();
    float tot = 0.0f;
    #pragma unroll
    for (int w = 0; w < 8; w++) tot += wsum[w];
    float nrm = sqrtf(tot);
    h = fmaxf(h / fmaxf(nrm, 1e-12f), 0.0f);

    __nv_bfloat16 hi = __float2bfloat16(h);
    size_t off = (size_t)i * D_DIM + t;
    g_Ah[off] = hi;
    g_Al[off] = __float2bfloat16(h - __bfloat162float(hi));
}

// ---------------- output GEMM: Out[M,32] = (Hh+Hl) @ W2 + b2 ---------------
__global__ __launch_bounds__(256)
void gemm_out_kernel(const float* __restrict__ W2,
                     const float* __restrict__ b2, float* __restrict__ Out, int M)
{
    extern __shared__ __align__(16) float smem[];
    float* sW = smem;                 // [256][32] (32KB)
    float* sH = smem + D_DIM * 32;    // [64][256] (64KB)

    int tid  = threadIdx.x;
    int brow = blockIdx.x * 64;

    #pragma unroll
    for (int l = 0; l < 8; l++) {
        int idx = tid + l * 256;
        reinterpret_cast<float4*>(sW)[idx] = reinterpret_cast<const float4*>(W2)[idx];
    }
    #pragma unroll
    for (int l = 0; l < 32; l++) {
        int idx = tid + l * 256;       // bf16x2 index into 64x256 (8192 total)
        int r = idx >> 7, c2 = idx & 127;
        float2 f = make_float2(0.f, 0.f);
        if (brow + r < M) {
            size_t off = (size_t)(brow + r) * D_DIM + c2 * 2;
            __nv_bfloat162 hv = *(const __nv_bfloat162*)(g_Ah + off);
            __nv_bfloat162 lv = *(const __nv_bfloat162*)(g_Al + off);
            f.x = __bfloat162float(hv.x) + __bfloat162float(lv.x);
            f.y = __bfloat162float(hv.y) + __bfloat162float(lv.y);
        }
        *reinterpret_cast<float2*>(sH + r * D_DIM + c2 * 2) = f;
    }
    __syncthreads();

    int ry = tid >> 3;            // 0..31; handles rows ry and ry+32
    int c4 = (tid & 7) * 4;
    float4 acc0 = make_float4(0.f, 0.f, 0.f, 0.f);
    float4 acc1 = make_float4(0.f, 0.f, 0.f, 0.f);
    #pragma unroll 8
    for (int k = 0; k < D_DIM; k++) {
        float4 w = *reinterpret_cast<const float4*>(&sW[k * 32 + c4]);
        float h0 = sH[ry * D_DIM + k];
        float h1 = sH[(ry + 32) * D_DIM + k];
        acc0.x = fmaf(h0, w.x, acc0.x); acc0.y = fmaf(h0, w.y, acc0.y);
        acc0.z = fmaf(h0, w.z, acc0.z); acc0.w = fmaf(h0, w.w, acc0.w);
        acc1.x = fmaf(h1, w.x, acc1.x); acc1.y = fmaf(h1, w.y, acc1.y);
        acc1.z = fmaf(h1, w.z, acc1.z); acc1.w = fmaf(h1, w.w, acc1.w);
    }
    float4 bb = *reinterpret_cast<const float4*>(b2 + c4);
    int grow0 = brow + ry, grow1 = brow + ry + 32;
    if (grow0 < M) {
        float4 o; o.x = acc0.x + bb.x; o.y = acc0.y + bb.y;
        o.z = acc0.z + bb.z; o.w = acc0.w + bb.w;
        *reinterpret_cast<float4*>(Out + (size_t)grow0 * O_DIM + c4) = o;
    }
    if (grow1 < M) {
        float4 o; o.x = acc1.x + bb.x; o.y = acc1.y + bb.y;
        o.z = acc1.z + bb.z; o.w = acc1.w + bb.w;
        *reinterpret_cast<float4*>(Out + (size_t)grow1 * O_DIM + c4) = o;
    }
}

// ---------------- host launcher (single stream) ----------------------------
typedef CUresult (CUDAAPI *PFN_encTiled)(
    CUtensorMap*, CUtensorMapDataType, cuuint32_t, void*,
    const cuuint64_t*, const cuuint64_t*, const cuuint32_t*, const cuuint32_t*,
    CUtensorMapInterleave, CUtensorMapSwizzle, CUtensorMapL2promotion,
    CUtensorMapFloatOOBfill);

extern "C" void kernel_launch(void* const* d_in, const int* in_sizes, int n_in,
                              void* d_out, int out_size)
{
    const float* x   = (const float*)d_in[0];
    const int*   ei  = (const int*)  d_in[1];
    const float* W0  = (const float*)d_in[2];
    const float* b0  = (const float*)d_in[3];
    const float* Wn0 = (const float*)d_in[4];
    const float* bn0 = (const float*)d_in[5];
    const float* W1  = (const float*)d_in[6];
    const float* b1  = (const float*)d_in[7];
    const float* Wn1 = (const float*)d_in[8];
    const float* bn1 = (const float*)d_in[9];
    const float* W2  = (const float*)d_in[10];
    const float* b2  = (const float*)d_in[11];

    int M = in_sizes[0] / D_DIM;
    int E = in_sizes[1] / 2;
    const int* erow = ei;
    const int* ecol = ei + E;

    float *pBiasC, *pDinv;
    __half *pBh, *pCh, *pYh;
    __nv_bfloat16 *pAh, *pAl, *pWh, *pWl;
    int *pCnt, *pBase;
    cudaGetSymbolAddress((void**)&pBh,   g_Bh);
    cudaGetSymbolAddress((void**)&pCh,   g_Ch);
    cudaGetSymbolAddress((void**)&pYh,   g_Yh);
    cudaGetSymbolAddress((void**)&pDinv, g_dinv);
    cudaGetSymbolAddress((void**)&pAh,   g_Ah);
    cudaGetSymbolAddress((void**)&pAl,   g_Al);
    cudaGetSymbolAddress((void**)&pWh,   g_Wh);
    cudaGetSymbolAddress((void**)&pWl,   g_Wl);
    cudaGetSymbolAddress((void**)&pBiasC, g_biasC);
    cudaGetSymbolAddress((void**)&pCnt,  g_cnt);
    cudaGetSymbolAddress((void**)&pBase, g_base);

    static CUtensorMap tmAh, tmAl, tmWh, tmWl;
    static bool init_done = false;
    if (!init_done) {
        cudaFuncSetAttribute(hmma_gemm_kernel,
                             cudaFuncAttributeMaxDynamicSharedMemorySize,
                             2 * STAGE_BYTES + 1024);
        cudaFuncSetAttribute(gemm_out_kernel,
                             cudaFuncAttributeMaxDynamicSharedMemorySize, 98304);

        void* fp = nullptr;
        cudaDriverEntryPointQueryResult qr;
#if CUDART_VERSION >= 12050
        cudaGetDriverEntryPointByVersion("cuTensorMapEncodeTiled", &fp, 12000,
                                         cudaEnableDefault, &qr);
#else
        cudaGetDriverEntryPoint("cuTensorMapEncodeTiled", &fp,
                                cudaEnableDefault, &qr);
#endif
        PFN_encTiled enc = (PFN_encTiled)fp;

        cuuint64_t dimsA[2] = {256, (cuuint64_t)M};
        cuuint64_t strA[1]  = {256 * 2};
        cuuint64_t dimsW[2] = {256, 1024};
        cuuint64_t strW[1]  = {256 * 2};
        cuuint32_t box[2]   = {64, 128};
        cuuint32_t estr[2]  = {1, 1};
        enc(&tmAh, CU_TENSOR_MAP_DATA_TYPE_BFLOAT16, 2, pAh, dimsA, strA, box,
            estr, CU_TENSOR_MAP_INTERLEAVE_NONE, CU_TENSOR_MAP_SWIZZLE_128B,
            CU_TENSOR_MAP_L2_PROMOTION_L2_128B, CU_TENSOR_MAP_FLOAT_OOB_FILL_NONE);
        enc(&tmAl, CU_TENSOR_MAP_DATA_TYPE_BFLOAT16, 2, pAl, dimsA, strA, box,
            estr, CU_TENSOR_MAP_INTERLEAVE_NONE, CU_TENSOR_MAP_SWIZZLE_128B,
            CU_TENSOR_MAP_L2_PROMOTION_L2_128B, CU_TENSOR_MAP_FLOAT_OOB_FILL_NONE);
        enc(&tmWh, CU_TENSOR_MAP_DATA_TYPE_BFLOAT16, 2, pWh, dimsW, strW, box,
            estr, CU_TENSOR_MAP_INTERLEAVE_NONE, CU_TENSOR_MAP_SWIZZLE_128B,
            CU_TENSOR_MAP_L2_PROMOTION_L2_128B, CU_TENSOR_MAP_FLOAT_OOB_FILL_NONE);
        enc(&tmWl, CU_TENSOR_MAP_DATA_TYPE_BFLOAT16, 2, pWl, dimsW, strW, box,
            estr, CU_TENSOR_MAP_INTERLEAVE_NONE, CU_TENSOR_MAP_SWIZZLE_128B,
            CU_TENSOR_MAP_L2_PROMOTION_L2_128B, CU_TENSOR_MAP_FLOAT_OOB_FILL_NONE);
        init_done = true;
    }

    int eb = (E + 255) / 256;
    int nb = (M + 255) / 256;
    dim3 gg((M + 127) / 128, 4);
    dim3 wfgrid(8, 8, 8), wfblk(32, 8);
    dim3 pgrid(8, 16, 2), pblk(32, 8);

    // CSR build + dinv (before GEMM: its epilogue reads dinv)
    cudaMemsetAsync(pCnt, 0, (size_t)M * sizeof(int));
    cudaMemsetAsync(pBase, 0, sizeof(int));
    count_edges_kernel<<<eb, 256>>>(erow, E);
    offsets_kernel<<<nb, 256>>>(M);
    fill_csr_kernel<<<eb, 256>>>(erow, ecol, E);

    // weight prep (both layers)
    fuse_wf_kernel<<<wfgrid, wfblk>>>(W0, Wn0, W1, Wn1);
    fuse_b_kernel<<<2, 256>>>(b0, Wn0, bn0, b1, Wn1, bn1);
    pack_w_kernel<<<pgrid, pblk>>>(W0, b0, W1, b1);

    // split input
    split_kernel<<<(M * D_DIM / 4 + 255) / 256, 256>>>(x, M * D_DIM / 4);

    // layer 1
    hmma_gemm_kernel<<<gg, 512, 2 * STAGE_BYTES + 1024>>>(
        tmAh, tmAl, tmWh, tmWl, 0, pBiasC, pBh, pCh, pYh, pDinv, M);
    agg_combine_kernel<<<M, 256>>>(pBh, pCh, pYh, M);

    // layer 2
    hmma_gemm_kernel<<<gg, 512, 2 * STAGE_BYTES + 1024>>>(
        tmAh, tmAl, tmWh, tmWl, 512, pBiasC + 512, pBh, pCh, pYh, pDinv, M);
    agg_combine_kernel<<<M, 256>>>(pBh, pCh, pYh, M);

    // output layer
    gemm_out_kernel<<<(M + 63) / 64, 256, 98304>>>(W2, b2, (float*)d_out, M);
}